// round 1
// baseline (speedup 1.0000x reference)
#include <cuda_runtime.h>
#include <cstdint>

#define B_   1024
#define T_   512
#define OBS_ 64
#define H_   256
#define A_   16
#define K1   192      // W_h k-rows resident in smem
#define KREG 64       // W_h k-rows resident in registers (packed f32x2)
#define BC   8        // batch rows per CTA (rnn kernel)
#define R1   32       // (b,t) rows per CTA (xproj kernel)

// x_proj scratch: [B][T][H] fp32 (512 MB, static device array — allowed)
__device__ float g_xp[(size_t)B_ * T_ * H_];

// ---------- packed f32x2 helpers ----------
__device__ __forceinline__ unsigned long long pk2(float x, float y) {
    unsigned long long r;
    asm("mov.b64 %0, {%1,%2};" : "=l"(r)
        : "r"(__float_as_uint(x)), "r"(__float_as_uint(y)));
    return r;
}
__device__ __forceinline__ unsigned long long ffma2(unsigned long long a,
                                                    unsigned long long b,
                                                    unsigned long long c) {
    unsigned long long d;
    asm("fma.rn.f32x2 %0, %1, %2, %3;" : "=l"(d) : "l"(a), "l"(b), "l"(c));
    return d;
}
__device__ __forceinline__ float lo2(unsigned long long v) { return __uint_as_float((unsigned)v); }
__device__ __forceinline__ float hi2(unsigned long long v) { return __uint_as_float((unsigned)(v >> 32)); }
__device__ __forceinline__ float sigf(float x) {
    return __fdividef(1.0f, 1.0f + __expf(-x));
}

// ============================================================================
// Kernel 1: x_proj[bt][j] = sum_k obs[bt][k] * W_in[j][k] + b_h[j]
// grid = B*T/R1 blocks, 256 threads; f32x2 packed over row pairs.
// ============================================================================
extern "C" __global__ void __launch_bounds__(256)
xproj_kernel(const float* __restrict__ obs, const float* __restrict__ W_in,
             const float* __restrict__ b_h) {
    extern __shared__ float sm1[];
    float* w_inT = sm1;              // [64][256]
    float* obsT  = sm1 + 64 * 256;   // [64][R1]
    const int tid = threadIdx.x;
    const size_t bt0 = (size_t)blockIdx.x * R1;

    // W_in transposed into smem: w_inT[k][j] = W_in[j][k]
#pragma unroll
    for (int i = 0; i < 64; i++) {
        int e = tid + i * 256;
        int jj = e & 255, k = e >> 8;
        w_inT[k * 256 + jj] = W_in[jj * OBS_ + k];
    }
    // obs tile transposed: obsT[k][r] = obs[bt0+r][k]
#pragma unroll
    for (int i = 0; i < (R1 * OBS_) / 256; i++) {
        int e = tid + i * 256;
        int r = e >> 6, k = e & 63;
        obsT[k * R1 + r] = obs[(bt0 + r) * OBS_ + k];
    }
    __syncthreads();

    const int j = tid;
    const float bias = b_h[j];
    unsigned long long acc[R1 / 2];
#pragma unroll
    for (int p = 0; p < R1 / 2; p++) acc[p] = pk2(bias, bias);

#pragma unroll 8
    for (int k = 0; k < OBS_; k++) {
        float w = w_inT[k * 256 + j];
        unsigned long long W2 = pk2(w, w);
        const ulonglong2* op = (const ulonglong2*)(obsT + k * R1);
#pragma unroll
        for (int q = 0; q < R1 / 4; q++) {
            ulonglong2 v = op[q];
            acc[2 * q]     = ffma2(v.x, W2, acc[2 * q]);
            acc[2 * q + 1] = ffma2(v.y, W2, acc[2 * q + 1]);
        }
    }
#pragma unroll
    for (int p = 0; p < R1 / 2; p++) {
        g_xp[(bt0 + 2 * p)     * H_ + j] = lo2(acc[p]);
        g_xp[(bt0 + 2 * p + 1) * H_ + j] = hi2(acc[p]);
    }
}

// ============================================================================
// Kernel 2: persistent recurrent kernel. 128 CTAs, each owns BC=8 batch rows
// for all T steps. W_h^T: 192 rows in smem + 64 rows as packed regs.
// Thread j computes pre_h[b][j] for all 8 rows (f32x2 packs row pairs).
// ============================================================================
extern "C" __global__ void __launch_bounds__(256)
rnn_kernel(const float* __restrict__ W_h, const float* __restrict__ W_out,
           const float* __restrict__ b_out, float* __restrict__ out) {
    extern __shared__ float sm2[];
    float* wT = sm2;                  // [K1][256]  wT[k][j] = W_h[j][k]
    float* hT = wT + K1 * 256;        // [256][8]   hT[k][b]
    float* hB = hT + 256 * 8;         // [8][256]   hB[b][k]
    float* Wo = hB + 8 * 256;         // [16][260]  padded rows (bank spread)

    const int tid = threadIdx.x, j = tid;
    const int bg0 = blockIdx.x * BC;

    // zero h state (hT + hB contiguous: 4096 floats)
#pragma unroll
    for (int i = 0; i < 16; i++) hT[tid + i * 256] = 0.0f;
    // W_out into padded smem
#pragma unroll
    for (int i = 0; i < 16; i++) {
        int e = tid + i * 256;
        int a = e >> 8, k = e & 255;
        Wo[a * 260 + k] = W_out[e];
    }
    // W_h^T (k < K1) into smem
    for (int k = 0; k < K1; k++) wT[k * 256 + tid] = W_h[tid * 256 + k];
    // overflow rows into registers, pre-packed (w,w)
    unsigned long long wreg2[KREG];
#pragma unroll
    for (int i = 0; i < KREG; i++) {
        float w = W_h[tid * 256 + K1 + i];
        wreg2[i] = pk2(w, w);
    }

    float hreg[8];
#pragma unroll
    for (int b = 0; b < 8; b++) hreg[b] = 0.0f;
    float oreg = 0.0f;
    const int ob = tid >> 4, oa = tid & 15;
    const float bo = (tid < 128) ? b_out[oa] : 0.0f;

    float xp_cur[8], xp_nxt[8];
#pragma unroll
    for (int b = 0; b < 8; b++)
        xp_cur[b] = g_xp[((size_t)(bg0 + b) * T_) * H_ + j];

    __syncthreads();

    for (int t = 0; t < T_; t++) {
        unsigned long long a0 = pk2(xp_cur[0], xp_cur[1]);
        unsigned long long a1 = pk2(xp_cur[2], xp_cur[3]);
        unsigned long long a2 = pk2(xp_cur[4], xp_cur[5]);
        unsigned long long a3 = pk2(xp_cur[6], xp_cur[7]);

        // prefetch next step's x_proj (latency hidden under the GEMM)
        const int tn = (t + 1 < T_) ? t + 1 : t;
#pragma unroll
        for (int b = 0; b < 8; b++)
            xp_nxt[b] = __ldg(&g_xp[((size_t)(bg0 + b) * T_ + tn) * H_ + j]);

        // ---- recurrent GEMM, smem-resident k ----
#pragma unroll 16
        for (int k = 0; k < K1; k++) {
            float w = wT[k * 256 + j];
            unsigned long long W2 = pk2(w, w);
            const ulonglong2* hp = (const ulonglong2*)(hT + k * 8);
            ulonglong2 u = hp[0], v = hp[1];
            a0 = ffma2(u.x, W2, a0);
            a1 = ffma2(u.y, W2, a1);
            a2 = ffma2(v.x, W2, a2);
            a3 = ffma2(v.y, W2, a3);
        }
        // ---- register-resident k ----
#pragma unroll
        for (int i = 0; i < KREG; i++) {
            const ulonglong2* hp = (const ulonglong2*)(hT + (K1 + i) * 8);
            ulonglong2 u = hp[0], v = hp[1];
            unsigned long long W2 = wreg2[i];
            a0 = ffma2(u.x, W2, a0);
            a1 = ffma2(u.y, W2, a1);
            a2 = ffma2(v.x, W2, a2);
            a3 = ffma2(v.y, W2, a3);
        }

        float pre[8] = {lo2(a0), hi2(a0), lo2(a1), hi2(a1),
                        lo2(a2), hi2(a2), lo2(a3), hi2(a3)};
#pragma unroll
        for (int b = 0; b < 8; b++) {
            float s = sigf(pre[b]);
            hreg[b] = 0.9f * hreg[b] + 0.1f * s;
        }

        __syncthreads();  // all reads of hT for step t complete
        // publish new h in both layouts
        float4* hTrow = (float4*)(hT + j * 8);
        hTrow[0] = make_float4(hreg[0], hreg[1], hreg[2], hreg[3]);
        hTrow[1] = make_float4(hreg[4], hreg[5], hreg[6], hreg[7]);
#pragma unroll
        for (int b = 0; b < 8; b++) hB[b * 256 + j] = hreg[b];
        __syncthreads();  // new h visible

        // ---- output projection: 128 threads, one (b,a) each ----
        if (tid < 128) {
            const float* hrow = hB + ob * 256;
            const float* wrow = Wo + oa * 260;
            unsigned long long oc = pk2(0.0f, 0.0f);
#pragma unroll 16
            for (int k = 0; k < 256; k += 4) {
                ulonglong2 hv = *(const ulonglong2*)(hrow + k);
                ulonglong2 wv = *(const ulonglong2*)(wrow + k);
                oc = ffma2(hv.x, wv.x, oc);
                oc = ffma2(hv.y, wv.y, oc);
            }
            float po = lo2(oc) + hi2(oc) + bo;
            float s = sigf(po);
            oreg = 0.9f * oreg + 0.1f * s;
            out[((size_t)(bg0 + ob) * T_ + t) * A_ + oa] = oreg;
        }

#pragma unroll
        for (int b = 0; b < 8; b++) xp_cur[b] = xp_nxt[b];
    }

    // final h, o (tuple order: out, h[1,B,H], o[1,B,A])
    const size_t HOFF = (size_t)B_ * T_ * A_;
    const size_t OOFF = HOFF + (size_t)B_ * H_;
#pragma unroll
    for (int b = 0; b < 8; b++)
        out[HOFF + (size_t)(bg0 + b) * H_ + j] = hreg[b];
    if (tid < 128)
        out[OOFF + (size_t)(bg0 + ob) * A_ + oa] = oreg;
}

// ============================================================================
extern "C" void kernel_launch(void* const* d_in, const int* in_sizes, int n_in,
                              void* d_out, int out_size) {
    const float* obs   = (const float*)d_in[0];
    const float* W_in  = (const float*)d_in[1];
    const float* W_h   = (const float*)d_in[2];
    const float* b_h   = (const float*)d_in[3];
    const float* W_out = (const float*)d_in[4];
    const float* b_out = (const float*)d_in[5];
    float* out = (float*)d_out;

    const int sm1b = (64 * 256 + 64 * R1) * 4;                       // 73728 B
    const int sm2b = (K1 * 256 + 256 * 8 + 8 * 256 + 16 * 260) * 4;  // 229632 B
    cudaFuncSetAttribute((const void*)xproj_kernel,
                         cudaFuncAttributeMaxDynamicSharedMemorySize, sm1b);
    cudaFuncSetAttribute((const void*)rnn_kernel,
                         cudaFuncAttributeMaxDynamicSharedMemorySize, sm2b);

    xproj_kernel<<<(B_ * T_) / R1, 256, sm1b>>>(obs, W_in, b_h);
    rnn_kernel<<<B_ / BC, 256, sm2b>>>(W_h, W_out, b_out, out);
}

// round 5
// speedup vs baseline: 1.6022x; 1.6022x over previous
#include <cuda_runtime.h>
#include <cstdint>

#define B_    1024
#define T_    512
#define OBS_  64
#define H_    256
#define A_    16

// rnn geometry: 256 threads = 8 warps, 2 k-groups x 128 column-pair threads
#define THREADS 256
#define KSM     80     // k's per group with W in smem
#define KR      48     // k's per group with W in registers

// smem offsets (floats) for rnn kernel
#define HT_OFF   0                    // hT[256][8]           (2048 f)
#define RED_OFF  2048                 // red[2][8][128] u64   (4096 f)
#define HB_OFF   6144                 // hB[8][260]           (2080 f)
#define ORED_OFF 8224                 // ored[256] u64        (512 f)
#define WO_OFF   8736                 // Wo[16][260]          (4160 f)
#define WP_OFF   12896                // wP[2][KSM][128] f2   (2*KSM*128*2 f)
#define SM2_FLOATS (WP_OFF + 2 * KSM * 128 * 2)   // 53856 f = 215424 B

// x_proj scratch: [B][T][H] fp32 (512 MB static device array — allowed)
__device__ float g_xp[(size_t)B_ * T_ * H_];

// ---------- packed f32x2 helpers ----------
__device__ __forceinline__ unsigned long long pk2(float x, float y) {
    unsigned long long r;
    asm("mov.b64 %0, {%1,%2};" : "=l"(r)
        : "r"(__float_as_uint(x)), "r"(__float_as_uint(y)));
    return r;
}
__device__ __forceinline__ unsigned long long ffma2(unsigned long long a,
                                                    unsigned long long b,
                                                    unsigned long long c) {
    unsigned long long d;
    asm("fma.rn.f32x2 %0, %1, %2, %3;" : "=l"(d) : "l"(a), "l"(b), "l"(c));
    return d;
}
__device__ __forceinline__ unsigned long long add2(unsigned long long a,
                                                   unsigned long long b) {
    unsigned long long d;
    asm("add.rn.f32x2 %0, %1, %2;" : "=l"(d) : "l"(a), "l"(b));
    return d;
}
__device__ __forceinline__ float lo2(unsigned long long v) { return __uint_as_float((unsigned)v); }
__device__ __forceinline__ float hi2(unsigned long long v) { return __uint_as_float((unsigned)(v >> 32)); }
// sigmoid via MUFU.TANH: sigma(x) = 0.5*tanh(x/2)+0.5
__device__ __forceinline__ float sigf(float x) {
    float t;
    asm("tanh.approx.f32 %0, %1;" : "=f"(t) : "f"(0.5f * x));
    return fmaf(0.5f, t, 0.5f);
}

// ============================================================================
// Kernel 1: x_proj[bt][j] = sum_k obs[bt][k] * W_in[j][k] + b_h[j]
// 2048 CTAs x 256 bt-rows each: W_in loaded ONCE per CTA, fully coalesced.
// ============================================================================
#define XROWS 256
#define XCH   32
extern "C" __global__ void __launch_bounds__(256)
xproj_kernel(const float* __restrict__ obs, const float* __restrict__ W_in,
             const float* __restrict__ b_h) {
    extern __shared__ float sm1[];
    float* w_inT = sm1;                  // [64][257] padded, conflict-free
    float* obsT  = sm1 + 64 * 257;       // [64][36]  padded
    const int tid = threadIdx.x;
    const size_t bt0 = (size_t)blockIdx.x * XROWS;

    // W_in: coalesced linear read, transposed scatter into padded smem
    const float* wsrc = W_in;
#pragma unroll
    for (int i = 0; i < 64; i++) {
        int e = tid + i * 256;           // e = jj*64 + k
        int jj = e >> 6, k = e & 63;
        w_inT[k * 257 + jj] = wsrc[e];
    }
    const int j = tid;
    const float bias = b_h[j];

    for (int ch = 0; ch < XROWS / XCH; ch++) {
        __syncthreads();
        // obs chunk: coalesced linear read, transposed into padded smem
        const float* osrc = obs + (bt0 + (size_t)ch * XCH) * OBS_;
#pragma unroll
        for (int i = 0; i < (XCH * OBS_) / 256; i++) {
            int e = tid + i * 256;       // e = r*64 + k
            int r = e >> 6, k = e & 63;
            obsT[k * 36 + r] = osrc[e];
        }
        __syncthreads();

        unsigned long long acc[XCH / 2];
#pragma unroll
        for (int q = 0; q < XCH / 2; q++) acc[q] = pk2(bias, bias);

#pragma unroll 4
        for (int k = 0; k < OBS_; k++) {
            float w = w_inT[k * 257 + j];
            unsigned long long W2 = pk2(w, w);
            const ulonglong2* op = (const ulonglong2*)(obsT + k * 36);
#pragma unroll
            for (int q = 0; q < XCH / 4; q++) {
                ulonglong2 v = op[q];
                acc[2 * q]     = ffma2(v.x, W2, acc[2 * q]);
                acc[2 * q + 1] = ffma2(v.y, W2, acc[2 * q + 1]);
            }
        }
        float* dst = g_xp + (bt0 + (size_t)ch * XCH) * H_ + j;
#pragma unroll
        for (int q = 0; q < XCH / 2; q++) {
            dst[(2 * q)     * H_] = lo2(acc[q]);
            dst[(2 * q + 1) * H_] = hi2(acc[q]);
        }
    }
}

// ============================================================================
// Kernel 2: persistent recurrent kernel. 128 CTAs x 256 threads (8 warps,
// perfectly SMSP-balanced). Each CTA owns 8 batch rows for all T steps.
// Phase 1 (GEMM): thread (g,p) computes partial pre_h for cols (2p,2p+1)
//                 over k in [128g,128g+128): 1024 FFMA2, uniform per thread.
// Phase 2 (combine): thread c reduces partials for column c, adds x_proj,
//                 sigmoid+EMA, publishes h to hT (k-major) and hB (b-major).
// Phase 3 (o):   thread = (b,a,k-half) half-dot + smem pairwise combine.
// ============================================================================
extern "C" __global__ void __launch_bounds__(THREADS, 1)
rnn_kernel(const float* __restrict__ W_h, const float* __restrict__ W_out,
           const float* __restrict__ b_out, float* __restrict__ out) {
    extern __shared__ float sm2[];
    float* hT = sm2 + HT_OFF;
    unsigned long long* red  = (unsigned long long*)(sm2 + RED_OFF);
    float* hB = sm2 + HB_OFF;
    unsigned long long* ored = (unsigned long long*)(sm2 + ORED_OFF);
    float* Wo = sm2 + WO_OFF;
    float2* wP = (float2*)(sm2 + WP_OFF);

    const int tid = threadIdx.x;
    const int g = tid >> 7, p = tid & 127;     // GEMM identity
    const int c = tid;                          // combine column
    const int bg0 = blockIdx.x * 8;

    // zero h state
#pragma unroll
    for (int i = 0; i < 8; i++) hT[tid + i * 256] = 0.0f;
    // W_out -> padded smem
#pragma unroll
    for (int i = 0; i < 16; i++) {
        int e = tid + i * 256;
        int a = e >> 8, k = e & 255;
        Wo[a * 260 + k] = W_out[e];
    }
    // W_h smem part: wP[g2][kk][pp] = (W_h[2pp][k], W_h[2pp+1][k]), k=128g2+kk
    for (int idx = tid; idx < 2 * KSM * 128; idx += THREADS) {
        int g2 = idx / (KSM * 128);
        int r  = idx - g2 * (KSM * 128);
        int kk = r >> 7, pp = r & 127;
        int k  = g2 * 128 + kk;
        wP[idx] = make_float2(W_h[(2 * pp) * 256 + k],
                              W_h[(2 * pp + 1) * 256 + k]);
    }
    // W_h register part (cols 2p, 2p+1; k = 128g + KSM + i)
    float wx[KR], wy[KR];
#pragma unroll
    for (int i = 0; i < KR; i++) {
        int k = g * 128 + KSM + i;
        wx[i] = W_h[(2 * p) * 256 + k];
        wy[i] = W_h[(2 * p + 1) * 256 + k];
    }

    // per-column h state (col c) and per-(b,a) o state
    float hr[8];
#pragma unroll
    for (int b = 0; b < 8; b++) hr[b] = 0.0f;
    const int ot = tid & 127, ohalf = tid >> 7;
    const int ob = ot >> 4, oa = ot & 15, okb = ohalf * 128;
    float oreg = 0.0f;
    const float obo = (tid < 128) ? b_out[oa] : 0.0f;

    // x_proj for col c, t=0
    float xp_cur[8];
#pragma unroll
    for (int b = 0; b < 8; b++)
        xp_cur[b] = g_xp[((size_t)(bg0 + b) * T_) * H_ + c];

    __syncthreads();

    const float2* wp = wP + g * (KSM * 128) + p;
    const ulonglong2* hp = (const ulonglong2*)hT + g * 256;
    const int p2 = c >> 1, e4 = (c & 1) * 4;

    for (int t = 0; t < T_; t++) {
        // ---- Phase 1: GEMM partials ----
        unsigned long long acc[8];
#pragma unroll
        for (int i = 0; i < 8; i++) acc[i] = 0ull;

#pragma unroll 8
        for (int kk = 0; kk < KSM; kk++) {
            float2 w2 = wp[kk * 128];
            unsigned long long W0 = pk2(w2.x, w2.x);
            unsigned long long W1 = pk2(w2.y, w2.y);
            ulonglong2 u = hp[2 * kk];
            ulonglong2 v = hp[2 * kk + 1];
            acc[0] = ffma2(u.x, W0, acc[0]);
            acc[1] = ffma2(u.y, W0, acc[1]);
            acc[2] = ffma2(v.x, W0, acc[2]);
            acc[3] = ffma2(v.y, W0, acc[3]);
            acc[4] = ffma2(u.x, W1, acc[4]);
            acc[5] = ffma2(u.y, W1, acc[5]);
            acc[6] = ffma2(v.x, W1, acc[6]);
            acc[7] = ffma2(v.y, W1, acc[7]);
        }
#pragma unroll
        for (int i = 0; i < KR; i++) {
            ulonglong2 u = hp[2 * (KSM + i)];
            ulonglong2 v = hp[2 * (KSM + i) + 1];
            unsigned long long W0 = pk2(wx[i], wx[i]);
            unsigned long long W1 = pk2(wy[i], wy[i]);
            acc[0] = ffma2(u.x, W0, acc[0]);
            acc[1] = ffma2(u.y, W0, acc[1]);
            acc[2] = ffma2(v.x, W0, acc[2]);
            acc[3] = ffma2(v.y, W0, acc[3]);
            acc[4] = ffma2(u.x, W1, acc[4]);
            acc[5] = ffma2(u.y, W1, acc[5]);
            acc[6] = ffma2(v.x, W1, acc[6]);
            acc[7] = ffma2(v.y, W1, acc[7]);
        }
        // export partials
#pragma unroll
        for (int i = 0; i < 8; i++) red[(g * 8 + i) * 128 + p] = acc[i];
        __syncthreads();   // A

        // ---- Phase 2: combine for column c ----
        {
            unsigned long long s[4];
#pragma unroll
            for (int q = 0; q < 4; q++) {
                unsigned long long a0 = red[(e4 + q) * 128 + p2];
                unsigned long long a1 = red[(8 + e4 + q) * 128 + p2];
                s[q] = add2(a0, a1);
                s[q] = add2(s[q], pk2(xp_cur[2 * q], xp_cur[2 * q + 1]));
            }
            // prefetch next step's x_proj (hidden under next GEMM)
            int tn = (t + 1 < T_) ? t + 1 : T_ - 1;
#pragma unroll
            for (int b = 0; b < 8; b++)
                xp_cur[b] = __ldg(&g_xp[((size_t)(bg0 + b) * T_ + tn) * H_ + c]);

#pragma unroll
            for (int q = 0; q < 4; q++) {
                hr[2 * q]     = 0.9f * hr[2 * q]     + 0.1f * sigf(lo2(s[q]));
                hr[2 * q + 1] = 0.9f * hr[2 * q + 1] + 0.1f * sigf(hi2(s[q]));
            }
            // publish h: hT (k-major for GEMM), hB (b-major for o-phase)
            float4* hrow = (float4*)(hT + c * 8);
            hrow[0] = make_float4(hr[0], hr[1], hr[2], hr[3]);
            hrow[1] = make_float4(hr[4], hr[5], hr[6], hr[7]);
#pragma unroll
            for (int b = 0; b < 8; b++) hB[b * 260 + c] = hr[b];
        }
        __syncthreads();   // B

        // ---- Phase 3: output projection (all threads, half-dot each) ----
        {
            unsigned long long oacc = 0ull;
            const ulonglong2* hv = (const ulonglong2*)(hB + ob * 260 + okb);
            const ulonglong2* wv = (const ulonglong2*)(Wo + oa * 260 + okb);
#pragma unroll
            for (int q = 0; q < 32; q++) {
                ulonglong2 h2 = hv[q];
                ulonglong2 w2 = wv[q];
                oacc = ffma2(h2.x, w2.x, oacc);
                oacc = ffma2(h2.y, w2.y, oacc);
            }
            ored[tid] = oacc;
            __syncthreads();   // C
            if (tid < 128) {
                unsigned long long q2 = ored[tid + 128];
                float po = lo2(oacc) + hi2(oacc) + lo2(q2) + hi2(q2) + obo;
                oreg = 0.9f * oreg + 0.1f * sigf(po);
                out[((size_t)(bg0 + ob) * T_ + t) * A_ + oa] = oreg;
            }
        }
    }

    // finals (tuple order: out[B,T,A], h[1,B,H], o[1,B,A])
    const size_t HOFF = (size_t)B_ * T_ * A_;
    const size_t OOFF = HOFF + (size_t)B_ * H_;
#pragma unroll
    for (int b = 0; b < 8; b++)
        out[HOFF + (size_t)(bg0 + b) * H_ + c] = hr[b];
    if (tid < 128)
        out[OOFF + (size_t)(bg0 + ob) * A_ + oa] = oreg;
}

// ============================================================================
extern "C" void kernel_launch(void* const* d_in, const int* in_sizes, int n_in,
                              void* d_out, int out_size) {
    const float* obs   = (const float*)d_in[0];
    const float* W_in  = (const float*)d_in[1];
    const float* W_h   = (const float*)d_in[2];
    const float* b_h   = (const float*)d_in[3];
    const float* W_out = (const float*)d_in[4];
    const float* b_out = (const float*)d_in[5];
    float* out = (float*)d_out;

    const int sm1b = (64 * 257 + 64 * 36) * 4;   // 75008 B
    const int sm2b = SM2_FLOATS * 4;             // 215424 B
    cudaFuncSetAttribute((const void*)xproj_kernel,
                         cudaFuncAttributeMaxDynamicSharedMemorySize, sm1b);
    cudaFuncSetAttribute((const void*)rnn_kernel,
                         cudaFuncAttributeMaxDynamicSharedMemorySize, sm2b);

    xproj_kernel<<<(B_ * T_) / XROWS, 256, sm1b>>>(obs, W_in, b_h);
    rnn_kernel<<<B_ / 8, THREADS, sm2b>>>(W_h, W_out, b_out, out);
}

// round 11
// speedup vs baseline: 9.2227x; 5.7562x over previous
#include <cuda_runtime.h>
#include <cuda_fp16.h>
#include <cstdint>

#define B_    1024
#define T_    512
#define OBS_  64
#define H_    256
#define A_    16

// ---------- helpers ----------
__device__ __forceinline__ uint32_t f2h2(float lo, float hi) {
    uint32_t r;
    asm("cvt.rn.f16x2.f32 %0, %1, %2;" : "=r"(r) : "f"(hi), "f"(lo));
    return r;
}
__device__ __forceinline__ float sigf(float x) {
    float t;
    asm("tanh.approx.f32 %0, %1;" : "=f"(t) : "f"(0.5f * x));
    return fmaf(0.5f, t, 0.5f);
}
// m16n8k16 row.col f32 += f16*f16
__device__ __forceinline__ void mma16816(float* c, const uint32_t* a,
                                         uint32_t b0, uint32_t b1) {
    asm("mma.sync.aligned.m16n8k16.row.col.f32.f16.f16.f32 "
        "{%0,%1,%2,%3}, {%4,%5,%6,%7}, {%8,%9}, {%0,%1,%2,%3};"
        : "+f"(c[0]), "+f"(c[1]), "+f"(c[2]), "+f"(c[3])
        : "r"(a[0]), "r"(a[1]), "r"(a[2]), "r"(a[3]), "r"(b0), "r"(b1));
}

// ============================================================================
// Persistent RNN kernel. 128 CTAs x 256 thr (8 warps). CTA owns 8 batch rows.
//   pre_h[256j, 8b] = W_h[256,256] @ h + W_in[256,64] @ obs_t   (20 k-tiles)
//   warp w owns j-rows [32w, 32w+32) : 2 m-tiles, full k, no reduction.
//   pre_o[16a, 8b]  = W_out[16,256] @ h_new : k split 2 tiles/warp + smem
//   reduce by warp 0. All weights persistent in registers as A-fragments.
//   h/obs passed between steps as fp16 pairs in double-buffered smem:
//   pair layout  s[p][n] = (x[2p,n], x[2p+1,n])  -> B-frag LDS conflict-free.
// ============================================================================
extern "C" __global__ void __launch_bounds__(256, 1)
rnn_kernel(const float* __restrict__ obs,  const float* __restrict__ W_in,
           const float* __restrict__ W_h,  const float* __restrict__ b_h,
           const float* __restrict__ W_out, const float* __restrict__ b_out,
           float* __restrict__ out)
{
    __shared__ uint32_t s_hp[2][128][8];   // h  pairs  [buf][k/2][b]
    __shared__ uint32_t s_ob[2][32][8];    // obs pairs [buf][k/2][b]
    __shared__ float    s_os[8][128];      // o partials [warp][a*8+b]

    const int tid  = threadIdx.x;
    const int w    = tid >> 5, lane = tid & 31;
    const int ln   = lane >> 2, lq = lane & 3;     // groupID / inGroup
    const int jbase = w * 32 + ln;
    const int bg0  = blockIdx.x * 8;

    // ---- persistent A-fragments: W_h [2 m-tiles][16 k-tiles][4 regs] ----
    uint32_t ah[2][16][4];
#pragma unroll
    for (int kt = 0; kt < 16; kt++) {
        const int k0 = kt * 16 + lq * 2;
#pragma unroll
        for (int m = 0; m < 2; m++) {
            const int r0 = jbase + m * 16, r1 = r0 + 8;
            float2 v00 = *(const float2*)&W_h[r0 * 256 + k0];
            float2 v10 = *(const float2*)&W_h[r1 * 256 + k0];
            float2 v01 = *(const float2*)&W_h[r0 * 256 + k0 + 8];
            float2 v11 = *(const float2*)&W_h[r1 * 256 + k0 + 8];
            ah[m][kt][0] = f2h2(v00.x, v00.y);
            ah[m][kt][1] = f2h2(v10.x, v10.y);
            ah[m][kt][2] = f2h2(v01.x, v01.y);
            ah[m][kt][3] = f2h2(v11.x, v11.y);
        }
    }
    // ---- W_in fragments [2][4][4] ----
    uint32_t ai[2][4][4];
#pragma unroll
    for (int kt = 0; kt < 4; kt++) {
        const int k0 = kt * 16 + lq * 2;
#pragma unroll
        for (int m = 0; m < 2; m++) {
            const int r0 = jbase + m * 16, r1 = r0 + 8;
            float2 v00 = *(const float2*)&W_in[r0 * 64 + k0];
            float2 v10 = *(const float2*)&W_in[r1 * 64 + k0];
            float2 v01 = *(const float2*)&W_in[r0 * 64 + k0 + 8];
            float2 v11 = *(const float2*)&W_in[r1 * 64 + k0 + 8];
            ai[m][kt][0] = f2h2(v00.x, v00.y);
            ai[m][kt][1] = f2h2(v10.x, v10.y);
            ai[m][kt][2] = f2h2(v01.x, v01.y);
            ai[m][kt][3] = f2h2(v11.x, v11.y);
        }
    }
    // ---- W_out fragments: k-tiles 2w, 2w+1 (16 a-rows = one m-tile) ----
    uint32_t ao[2][4];
#pragma unroll
    for (int i = 0; i < 2; i++) {
        const int k0 = (w * 2 + i) * 16 + lq * 2;
        float2 v00 = *(const float2*)&W_out[ln * 256 + k0];
        float2 v10 = *(const float2*)&W_out[(ln + 8) * 256 + k0];
        float2 v01 = *(const float2*)&W_out[ln * 256 + k0 + 8];
        float2 v11 = *(const float2*)&W_out[(ln + 8) * 256 + k0 + 8];
        ao[i][0] = f2h2(v00.x, v00.y);
        ao[i][1] = f2h2(v10.x, v10.y);
        ao[i][2] = f2h2(v01.x, v01.y);
        ao[i][3] = f2h2(v11.x, v11.y);
    }

    // bias per owned j-row, o-bias for warp 0 reducer
    float bh[4];
#pragma unroll
    for (int ri = 0; ri < 4; ri++) bh[ri] = b_h[jbase + 8 * ri];
    const float bo = (w == 0) ? b_out[lane >> 1] : 0.0f;

    // EMA state (fp32, exact)
    float hs[4][2];
#pragma unroll
    for (int ri = 0; ri < 4; ri++) { hs[ri][0] = 0.0f; hs[ri][1] = 0.0f; }
    float oreg[4] = {0.0f, 0.0f, 0.0f, 0.0f};

    // zero h buffers (h_{-1} = 0); preload obs(0) into buf 0
#pragma unroll
    for (int i = 0; i < 8; i++)
        ((uint32_t*)s_hp)[tid + i * 256] = 0u;
    {
        const int b = tid & 7, kk = tid >> 3;
        float2 v = *(const float2*)&obs[((size_t)(bg0 + b) * T_) * OBS_ + kk * 2];
        s_ob[0][kk][b] = f2h2(v.x, v.y);
    }
    __syncthreads();

    const int pb = tid & 7, pk = tid >> 3;   // obs prefetch identity

    for (int t = 0; t < T_; t++) {
        const int cur = t & 1, nxt = cur ^ 1;

        // prefetch obs(t+1) (gmem -> regs, hidden under GEMM)
        const int tn = (t + 1 < T_) ? t + 1 : T_ - 1;
        float2 opf = *(const float2*)
            &obs[((size_t)(bg0 + pb) * T_ + tn) * OBS_ + pk * 2];

        // ---- h-GEMM: 20 k-tiles, 4 independent accum chains ----
        float c00[4] = {0,0,0,0}, c01[4] = {0,0,0,0};
        float c10[4] = {0,0,0,0}, c11[4] = {0,0,0,0};
        {
            const uint32_t (*hp)[8] = s_hp[cur];
#pragma unroll
            for (int kt = 0; kt < 16; kt++) {
                uint32_t b0 = hp[kt * 8 + lq][ln];
                uint32_t b1 = hp[kt * 8 + 4 + lq][ln];
                if (kt & 1) { mma16816(c01, ah[0][kt], b0, b1);
                              mma16816(c11, ah[1][kt], b0, b1); }
                else        { mma16816(c00, ah[0][kt], b0, b1);
                              mma16816(c10, ah[1][kt], b0, b1); }
            }
            const uint32_t (*ob)[8] = s_ob[cur];
#pragma unroll
            for (int kt = 0; kt < 4; kt++) {
                uint32_t b0 = ob[kt * 8 + lq][ln];
                uint32_t b1 = ob[kt * 8 + 4 + lq][ln];
                if (kt & 1) { mma16816(c01, ai[0][kt], b0, b1);
                              mma16816(c11, ai[1][kt], b0, b1); }
                else        { mma16816(c00, ai[0][kt], b0, b1);
                              mma16816(c10, ai[1][kt], b0, b1); }
            }
        }

        // ---- epilogue: EMA update + publish h_t (fp16 pairs, buf nxt) ----
        {
            uint16_t* hp16 = (uint16_t*)s_hp[nxt];
#pragma unroll
            for (int tile = 0; tile < 2; tile++) {
                const float* ca = tile ? c10 : c00;
                const float* cb = tile ? c11 : c01;
#pragma unroll
                for (int e = 0; e < 4; e++) {
                    const int ri = tile * 2 + (e >> 1), par = e & 1;
                    float pre = ca[e] + cb[e] + bh[ri];
                    float hn = 0.9f * hs[ri][par] + 0.1f * sigf(pre);
                    hs[ri][par] = hn;
                    const int j = jbase + 8 * ri, b = 2 * lq + par;
                    hp16[((j >> 1) * 8 + b) * 2 + (j & 1)] =
                        __half_as_ushort(__float2half_rn(hn));
                }
            }
            // publish obs(t+1)
            s_ob[nxt][pk][pb] = f2h2(opf.x, opf.y);
        }
        __syncthreads();   // bar1: h_t + obs(t+1) visible

        // ---- o-GEMM: 2 k-tiles per warp on h_t, partials to smem ----
        {
            float co[4] = {0,0,0,0};
            const uint32_t (*hp)[8] = s_hp[nxt];
#pragma unroll
            for (int i = 0; i < 2; i++) {
                const int kt = w * 2 + i;
                uint32_t b0 = hp[kt * 8 + lq][ln];
                uint32_t b1 = hp[kt * 8 + 4 + lq][ln];
                mma16816(co, ao[i], b0, b1);
            }
            *(float2*)&s_os[w][ln * 8 + 2 * lq]      = make_float2(co[0], co[1]);
            *(float2*)&s_os[w][64 + ln * 8 + 2 * lq] = make_float2(co[2], co[3]);
        }
        __syncthreads();   // bar2: partials visible

        if (w == 0) {      // reduce 8 warps, o-EMA, store out[b][t][a]
            float4 s = make_float4(0.f, 0.f, 0.f, 0.f);
#pragma unroll
            for (int ww = 0; ww < 8; ww++) {
                float4 v = *(const float4*)&s_os[ww][lane * 4];
                s.x += v.x; s.y += v.y; s.z += v.z; s.w += v.w;
            }
            const int a = lane >> 1;
            float pq[4] = {s.x, s.y, s.z, s.w};
#pragma unroll
            for (int q = 0; q < 4; q++) {
                float on = 0.9f * oreg[q] + 0.1f * sigf(pq[q] + bo);
                oreg[q] = on;
                const int b = (lane & 1) * 4 + q;
                out[((size_t)(bg0 + b) * T_ + t) * A_ + a] = on;
            }
        }
    }

    // ---- finals (tuple order: out[B,T,A], h[1,B,H], o[1,B,A]) ----
    const size_t HOFF = (size_t)B_ * T_ * A_;
    const size_t OOFF = HOFF + (size_t)B_ * H_;
#pragma unroll
    for (int ri = 0; ri < 4; ri++) {
        const int j = jbase + 8 * ri;
#pragma unroll
        for (int par = 0; par < 2; par++) {
            const int b = 2 * lq + par;
            out[HOFF + (size_t)(bg0 + b) * H_ + j] = hs[ri][par];
        }
    }
    if (w == 0) {
        const int a = lane >> 1;
#pragma unroll
        for (int q = 0; q < 4; q++) {
            const int b = (lane & 1) * 4 + q;
            out[OOFF + (size_t)(bg0 + b) * A_ + a] = oreg[q];
        }
    }
}

// ============================================================================
extern "C" void kernel_launch(void* const* d_in, const int* in_sizes, int n_in,
                              void* d_out, int out_size) {
    const float* obs   = (const float*)d_in[0];
    const float* W_in  = (const float*)d_in[1];
    const float* W_h   = (const float*)d_in[2];
    const float* b_h   = (const float*)d_in[3];
    const float* W_out = (const float*)d_in[4];
    const float* b_out = (const float*)d_in[5];
    float* out = (float*)d_out;

    rnn_kernel<<<B_ / 8, 256>>>(obs, W_in, W_h, b_h, W_out, b_out, out);
}